// round 14
// baseline (speedup 1.0000x reference)
#include <cuda_runtime.h>

#define NUM_C 19
#define NUM_A 512            // feature channels
#define A4 (NUM_A / 4)       // float4 per row = 128
#define GRID1 148            // accum blocks: 1 per SM
#define NFIN  (NUM_C * 8)    // finalize blocks: 152
#define TPB1 512             // 4 warpgroups of 128 threads
#define CPAD 20              // padded class stride for count buckets

// Dynamic smem layout:
//   float4 ssum[4][NUM_C * A4]   (155648 B)  per-warpgroup replicas
//   float  scnt[16][CPAD]        (1280 B)    per-warp count buckets
//   int    slab[rowsb]           (~14.2 KB)  this block's label slice
#define SMEM_SSUM_F4 (4 * NUM_C * A4)
#define SMEM_BASE_BYTES (SMEM_SSUM_F4 * 16 + 16 * CPAD * 4)

// Deterministic partial-sum scratch (no device-side allocation allowed).
__device__ float g_psums[(size_t)GRID1 * NUM_C * NUM_A]; // [g][c][a]  ~5.8 MB
__device__ float g_pcnts[GRID1 * NUM_C];                 // [g][c]
__device__ int   g_done;                                 // accum blocks finished
__device__ int   g_fin;                                  // finalize blocks past gate

// ---- 8-row batch helpers. Labels come from SMEM (29-cyc LDS) so the
// ---- feature-load predicate never waits on a DRAM label load.
#define LOAD_BATCH(RR, LAB, F)                                              \
    do {                                                                    \
        const int _rel = (RR) - r0b;                                        \
        _Pragma("unroll")                                                   \
        for (int j = 0; j < 8; j++) LAB[j] = slab[_rel + j];                \
        _Pragma("unroll")                                                   \
        for (int j = 0; j < 8; j++)                                         \
            if (LAB[j] != ign)                                              \
                F[j] = __ldcs(&feat[(size_t)((RR) + j) * A4 + tt]);         \
    } while (0)

#define RMW_BATCH(LAB, F)                                                   \
    do {                                                                    \
        _Pragma("unroll")                                                   \
        for (int j = 0; j < 8; j++) {                                       \
            if (LAB[j] != ign) {                                            \
                const int idx = LAB[j] * A4 + tt;                           \
                float4 s = ssum[idx];                                       \
                s.x += F[j].x; s.y += F[j].y; s.z += F[j].z; s.w += F[j].w; \
                ssum[idx] = s;                                              \
            }                                                               \
        }                                                                   \
        if (lane == 0) {                                                    \
            _Pragma("unroll")                                               \
            for (int j = 0; j < 2; j++) {                                   \
                const int jj = wgw * 2 + j;                                 \
                if (LAB[jj] != ign) scnt[warp * CPAD + LAB[jj]] += 1.f;     \
            }                                                               \
        }                                                                   \
    } while (0)

__device__ __forceinline__ void accum_part(
    const float4* __restrict__ feat,
    const int*    __restrict__ labels,
    const int*    __restrict__ ignore_ptr,
    int N, float4* smem4)
{
    const int t    = threadIdx.x;
    const int wg   = t >> 7;        // warpgroup 0..3
    const int tt   = t & 127;       // float4 channel within warpgroup
    const int warp = t >> 5;        // 0..15
    const int wgw  = warp & 3;      // warp within warpgroup
    const int lane = t & 31;

    float4* ssum = smem4 + (size_t)wg * (NUM_C * A4);     // this wg's replica
    float*  scnt = (float*)(smem4 + SMEM_SSUM_F4);        // [16][CPAD]
    int*    slab = (int*)(scnt + 16 * CPAD);              // [rowsb]

    const int ign   = *ignore_ptr;
    // rows per block rounded to 32 so warpgroup chunks stay 8-aligned
    const int rowsb = (((N + GRID1 - 1) / GRID1) + 31) & ~31;
    const int r0b   = blockIdx.x * rowsb;
    const int r1b   = min(r0b + rowsb, N);
    const int nb    = max(r1b - r0b, 0);

    // ---- prologue: stage this block's labels into smem (coalesced int4) ----
    {
        const int4* lsrc = (const int4*)(labels + r0b);
        int4*       ldst = (int4*)slab;
        const int   n4f  = nb >> 2;                     // full int4s
        for (int i = t; i < n4f; i += TPB1)
            ldst[i] = __ldg(&lsrc[i]);
        for (int i = (n4f << 2) + t; i < nb; i += TPB1) // remainder (<4)
            slab[i] = __ldg(&labels[r0b + i]);
    }
    #pragma unroll
    for (int i = t; i < SMEM_SSUM_F4; i += TPB1)
        smem4[i] = make_float4(0.f, 0.f, 0.f, 0.f);
    if (t < 16 * CPAD) scnt[t] = 0.f;
    __syncthreads();

    // per-warpgroup quarter of the block chunk, 8-aligned
    int chunk = (nb + 3) >> 2;
    chunk = (chunk + 7) & ~7;
    const int r0 = min(r0b + wg * chunk, r1b);
    const int r1 = min(r0 + chunk, r1b);

    const int nfull = (r1 - r0) >> 3;       // full 8-row batches

    int    labA[8], labB[8];
    float4 fA[8],   fB[8];

    if (nfull > 0) LOAD_BATCH(r0, labA, fA);

    int b = 0;
    // Pipelined main loop: prefetch batch b+1 before consuming batch b.
    for (; b + 2 < nfull; b += 2) {
        LOAD_BATCH(r0 + (b + 1) * 8, labB, fB);
        RMW_BATCH(labA, fA);
        LOAD_BATCH(r0 + (b + 2) * 8, labA, fA);
        RMW_BATCH(labB, fB);
    }
    if (nfull > 0) {
        if (b + 1 < nfull) {
            LOAD_BATCH(r0 + (b + 1) * 8, labB, fB);
            RMW_BATCH(labA, fA);
            RMW_BATCH(labB, fB);
        } else {
            RMW_BATCH(labA, fA);
        }
    }
    // scalar tail
    for (int r = r0 + nfull * 8; r < r1; r++) {
        const int lab = slab[r - r0b];
        if (lab != ign) {
            float4 f = __ldcs(&feat[(size_t)r * A4 + tt]);
            const int idx = lab * A4 + tt;
            float4 s = ssum[idx];
            s.x += f.x; s.y += f.y; s.z += f.z; s.w += f.w;
            ssum[idx] = s;
            if (tt == 0) scnt[(wg * 4) * CPAD + lab] += 1.f;
        }
    }
    __syncthreads();

    // Reduce the 4 warpgroup replicas and store one slab per block.
    float4* pout = reinterpret_cast<float4*>(g_psums) + (size_t)blockIdx.x * NUM_C * A4;
    #pragma unroll
    for (int i = t; i < NUM_C * A4; i += TPB1) {
        float4 a  = smem4[i];
        float4 bb = smem4[i + NUM_C * A4];
        float4 c4 = smem4[i + 2 * NUM_C * A4];
        float4 d  = smem4[i + 3 * NUM_C * A4];
        a.x = (a.x + bb.x) + (c4.x + d.x);
        a.y = (a.y + bb.y) + (c4.y + d.y);
        a.z = (a.z + bb.z) + (c4.z + d.z);
        a.w = (a.w + bb.w) + (c4.w + d.w);
        pout[i] = a;
    }
    if (t < NUM_C) {
        float cl = 0.f;
        #pragma unroll
        for (int w = 0; w < 16; w++) cl += scnt[w * CPAD + t];
        g_pcnts[blockIdx.x * NUM_C + t] = cl;
    }
    __syncthreads();
    __threadfence();                       // release psums/pcnts
    if (t == 0) atomicAdd(&g_done, 1);
}

__device__ __forceinline__ void finalize_part(float* __restrict__ out, float4* smem4)
{
    const int fb   = blockIdx.x - GRID1;   // 0..151
    const int c    = fb >> 3;              // class
    const int agrp = fb & 7;               // 16-float4 channel group
    const int t    = threadIdx.x;
    const int a4   = t & 15;    // 0..15
    const int gp   = t >> 4;    // 0..31
    const int warp = t >> 5;    // 0..15
    const int lane = t & 31;

    float4* red = smem4;                   // [32][16]
    __shared__ float wcnt[16];

    // ---- gate: wait for all accum blocks ----
    if (t == 0) {
        while (atomicAdd(&g_done, 0) < GRID1)
            __nanosleep(256);
    }
    __syncthreads();
    __threadfence();                       // acquire psums/pcnts

    const float4* ps = reinterpret_cast<const float4*>(g_psums);
    const size_t stride = (size_t)NUM_C * A4;
    const size_t off    = (size_t)c * A4 + agrp * 16 + a4;

    // ---- per-class count: one load per thread, warp-reduced ----
    {
        float cl = (t < GRID1) ? g_pcnts[t * NUM_C + c] : 0.f;
        #pragma unroll
        for (int o = 16; o > 0; o >>= 1)
            cl += __shfl_down_sync(0xFFFFFFFFu, cl, o);
        if (lane == 0) wcnt[warp] = cl;
    }

    // ---- partial-sum reduction: g = gp + 32*k, k = 0..3, + pred g = 128+gp ----
    const float4* base = ps + off + (size_t)gp * stride;
    float4 v0 = base[0];
    float4 v1 = base[(size_t)32 * stride];
    float4 v2 = base[(size_t)64 * stride];
    float4 v3 = base[(size_t)96 * stride];
    float4 v4 = make_float4(0.f, 0.f, 0.f, 0.f);
    if (gp < GRID1 - 128)
        v4 = base[(size_t)128 * stride];

    float4 acc;
    acc.x = (v0.x + v1.x) + (v2.x + v3.x) + v4.x;
    acc.y = (v0.y + v1.y) + (v2.y + v3.y) + v4.y;
    acc.z = (v0.z + v1.z) + (v2.z + v3.z) + v4.z;
    acc.w = (v0.w + v1.w) + (v2.w + v3.w) + v4.w;
    red[gp * 16 + a4] = acc;
    __syncthreads();

    #pragma unroll
    for (int s = 16; s > 0; s >>= 1) {
        if (gp < s) {
            float4 a = red[gp * 16 + a4];
            float4 b = red[(gp + s) * 16 + a4];
            a.x += b.x; a.y += b.y; a.z += b.z; a.w += b.w;
            red[gp * 16 + a4] = a;
        }
        __syncthreads();
    }

    if (t < 16) {
        float cnt = 0.f;
        #pragma unroll
        for (int w = 0; w < 16; w++) cnt += wcnt[w];
        const float inv = 1.f / ((cnt == 0.f) ? 1.f : cnt);
        float4 sum = red[a4];
        float4 mean = make_float4(sum.x * inv, sum.y * inv, sum.z * inv, sum.w * inv);

        float4* out4 = reinterpret_cast<float4*>(out);
        const int oidx = c * A4 + agrp * 16 + a4;
        out4[oidx] = mean;                                         // mean (C, A)
        out4[NUM_C * A4 + oidx] = make_float4(cnt, cnt, cnt, cnt); // sum_weight
        if (t == 0 && agrp == 0)
            out[2 * NUM_C * NUM_A + c] = cnt;                      // class_dist (C,)
    }

    // ---- counter self-reset so graph replays start from zero ----
    if (t == 0) {
        const int v = atomicAdd(&g_fin, 1);
        if (v == NFIN - 1) {               // all finalize blocks passed the gate
            g_fin  = 0;
            g_done = 0;
            __threadfence();
        }
    }
}

__global__ void __launch_bounds__(TPB1, 1) bars_fused_kernel(
    const float4* __restrict__ feat,
    const int*    __restrict__ labels,
    const int*    __restrict__ ignore_ptr,
    int N, float* __restrict__ out)
{
    extern __shared__ float4 smem4[];
    if (blockIdx.x < GRID1)
        accum_part(feat, labels, ignore_ptr, N, smem4);
    else
        finalize_part(out, smem4);
}

extern "C" void kernel_launch(void* const* d_in, const int* in_sizes, int n_in,
                              void* d_out, int out_size)
{
    const float4* feat   = (const float4*)d_in[0];
    const int*    labels = (const int*)d_in[1];
    const int*    ign    = (const int*)d_in[2];
    float*        out    = (float*)d_out;

    const int N = in_sizes[0] / NUM_A;

    // Label slice size must match the kernel's rowsb computation.
    const int rowsb = (((N + GRID1 - 1) / GRID1) + 31) & ~31;
    const int smem_bytes = SMEM_BASE_BYTES + rowsb * 4;

    cudaFuncSetAttribute(bars_fused_kernel,
                         cudaFuncAttributeMaxDynamicSharedMemorySize, smem_bytes);

    bars_fused_kernel<<<GRID1 + NFIN, TPB1, smem_bytes>>>(feat, labels, ign, N, out);
}

// round 15
// speedup vs baseline: 1.0360x; 1.0360x over previous
#include <cuda_runtime.h>

#define NUM_C 19
#define NUM_A 512            // feature channels
#define A4 (NUM_A / 4)       // float4 per row = 128
#define GRID1 148            // accum blocks: 1 per SM
#define NFIN  (NUM_C * 8)    // finalize blocks: 152
#define TPB1 512             // 4 warpgroups of 128 threads
#define CPAD 20              // padded class stride for count buckets

// Per-warpgroup replica layout inside dynamic smem:
//   float4 ssum[4][NUM_C * A4]   (155648 B)
//   float  scnt[16][CPAD]        (1280 B)
#define SMEM_SSUM_F4 (4 * NUM_C * A4)
#define SMEM_BYTES   (SMEM_SSUM_F4 * 16 + 16 * CPAD * 4)

// Deterministic partial-sum scratch (no device-side allocation allowed).
__device__ float g_psums[(size_t)GRID1 * NUM_C * NUM_A]; // [g][c][a]  ~5.8 MB
__device__ float g_pcnts[GRID1 * NUM_C];                 // [g][c]
__device__ int   g_done;                                 // accum blocks finished
__device__ int   g_fin;                                  // finalize blocks past gate

// ---- 8-row batch helpers (software pipeline) ----
#define LOAD_BATCH(RR, LAB, F)                                              \
    do {                                                                    \
        const int4 L0 = __ldg((const int4*)&labels[(RR)]);                  \
        const int4 L1 = __ldg((const int4*)&labels[(RR) + 4]);              \
        LAB[0] = L0.x; LAB[1] = L0.y; LAB[2] = L0.z; LAB[3] = L0.w;         \
        LAB[4] = L1.x; LAB[5] = L1.y; LAB[6] = L1.z; LAB[7] = L1.w;         \
        _Pragma("unroll")                                                   \
        for (int j = 0; j < 8; j++)                                         \
            if (LAB[j] != ign)                                              \
                F[j] = __ldcs(&feat[(size_t)((RR) + j) * A4 + tt]);         \
    } while (0)

#define RMW_BATCH(LAB, F)                                                   \
    do {                                                                    \
        _Pragma("unroll")                                                   \
        for (int j = 0; j < 8; j++) {                                       \
            if (LAB[j] != ign) {                                            \
                const int idx = LAB[j] * A4 + tt;                           \
                float4 s = ssum[idx];                                       \
                s.x += F[j].x; s.y += F[j].y; s.z += F[j].z; s.w += F[j].w; \
                ssum[idx] = s;                                              \
            }                                                               \
        }                                                                   \
        if (lane == 0) {                                                    \
            _Pragma("unroll")                                               \
            for (int j = 0; j < 2; j++) {                                   \
                const int jj = wgw * 2 + j;                                 \
                if (LAB[jj] != ign) scnt[warp * CPAD + LAB[jj]] += 1.f;     \
            }                                                               \
        }                                                                   \
    } while (0)

__device__ __forceinline__ void accum_part(
    const float4* __restrict__ feat,
    const int*    __restrict__ labels,
    const int*    __restrict__ ignore_ptr,
    int N, float4* smem4)
{
    const int t    = threadIdx.x;
    const int wg   = t >> 7;        // warpgroup 0..3
    const int tt   = t & 127;       // float4 channel within warpgroup
    const int warp = t >> 5;        // 0..15
    const int wgw  = warp & 3;      // warp within warpgroup
    const int lane = t & 31;

    float4* ssum = smem4 + (size_t)wg * (NUM_C * A4);     // this wg's replica
    float*  scnt = (float*)(smem4 + SMEM_SSUM_F4);        // [16][CPAD]

    #pragma unroll
    for (int i = t; i < SMEM_SSUM_F4; i += TPB1)
        smem4[i] = make_float4(0.f, 0.f, 0.f, 0.f);
    if (t < 16 * CPAD) scnt[t] = 0.f;
    __syncthreads();

    const int ign   = *ignore_ptr;
    // rows per block rounded to 32 so warpgroup chunks stay 8-aligned
    const int rowsb = (((N + GRID1 - 1) / GRID1) + 31) & ~31;
    const int r0b   = blockIdx.x * rowsb;
    const int r1b   = min(r0b + rowsb, N);

    const int nb    = max(r1b - r0b, 0);
    int chunk = (nb + 3) >> 2;
    chunk = (chunk + 7) & ~7;                             // 8-aligned
    const int r0    = min(r0b + wg * chunk, r1b);
    const int r1    = min(r0 + chunk, r1b);

    const int nfull = (r1 - r0) >> 3;       // full 8-row batches

    int    labA[8], labB[8];
    float4 fA[8],   fB[8];

    if (nfull > 0) LOAD_BATCH(r0, labA, fA);

    int b = 0;
    // Pipelined main loop: prefetch batch b+1 before consuming batch b.
    for (; b + 2 < nfull; b += 2) {
        LOAD_BATCH(r0 + (b + 1) * 8, labB, fB);
        RMW_BATCH(labA, fA);
        LOAD_BATCH(r0 + (b + 2) * 8, labA, fA);
        RMW_BATCH(labB, fB);
    }
    if (nfull > 0) {
        if (b + 1 < nfull) {
            LOAD_BATCH(r0 + (b + 1) * 8, labB, fB);
            RMW_BATCH(labA, fA);
            RMW_BATCH(labB, fB);
        } else {
            RMW_BATCH(labA, fA);
        }
    }
    // scalar tail
    for (int r = r0 + nfull * 8; r < r1; r++) {
        const int lab = __ldg(&labels[r]);
        if (lab != ign) {
            float4 f = __ldcs(&feat[(size_t)r * A4 + tt]);
            const int idx = lab * A4 + tt;
            float4 s = ssum[idx];
            s.x += f.x; s.y += f.y; s.z += f.z; s.w += f.w;
            ssum[idx] = s;
            if (tt == 0) scnt[(wg * 4) * CPAD + lab] += 1.f;
        }
    }
    __syncthreads();

    // Reduce the 4 warpgroup replicas and store one slab per block.
    float4* pout = reinterpret_cast<float4*>(g_psums) + (size_t)blockIdx.x * NUM_C * A4;
    #pragma unroll
    for (int i = t; i < NUM_C * A4; i += TPB1) {
        float4 a  = smem4[i];
        float4 bb = smem4[i + NUM_C * A4];
        float4 c4 = smem4[i + 2 * NUM_C * A4];
        float4 d  = smem4[i + 3 * NUM_C * A4];
        a.x = (a.x + bb.x) + (c4.x + d.x);
        a.y = (a.y + bb.y) + (c4.y + d.y);
        a.z = (a.z + bb.z) + (c4.z + d.z);
        a.w = (a.w + bb.w) + (c4.w + d.w);
        pout[i] = a;
    }
    if (t < NUM_C) {
        float cl = 0.f;
        #pragma unroll
        for (int w = 0; w < 16; w++) cl += scnt[w * CPAD + t];
        g_pcnts[blockIdx.x * NUM_C + t] = cl;
    }
    __syncthreads();
    __threadfence();                       // release psums/pcnts
    if (t == 0) atomicAdd(&g_done, 1);
}

__device__ __forceinline__ void finalize_part(float* __restrict__ out, float4* smem4)
{
    const int fb   = blockIdx.x - GRID1;   // 0..151
    const int c    = fb >> 3;              // class
    const int agrp = fb & 7;               // 16-float4 channel group
    const int t    = threadIdx.x;
    const int a4   = t & 15;    // 0..15
    const int gp   = t >> 4;    // 0..31
    const int warp = t >> 5;    // 0..15
    const int lane = t & 31;

    float4* red = smem4;                   // [32][16]
    __shared__ float wcnt[16];

    // ---- gate: wait for all accum blocks ----
    if (t == 0) {
        while (atomicAdd(&g_done, 0) < GRID1)
            __nanosleep(256);
    }
    __syncthreads();
    __threadfence();                       // acquire psums/pcnts

    const float4* ps = reinterpret_cast<const float4*>(g_psums);
    const size_t stride = (size_t)NUM_C * A4;
    const size_t off    = (size_t)c * A4 + agrp * 16 + a4;

    // ---- per-class count: one load per thread, warp-reduced ----
    {
        float cl = (t < GRID1) ? g_pcnts[t * NUM_C + c] : 0.f;
        #pragma unroll
        for (int o = 16; o > 0; o >>= 1)
            cl += __shfl_down_sync(0xFFFFFFFFu, cl, o);
        if (lane == 0) wcnt[warp] = cl;
    }

    // ---- partial-sum reduction: g = gp + 32*k, k = 0..3, + pred g = 128+gp ----
    const float4* base = ps + off + (size_t)gp * stride;
    float4 v0 = base[0];
    float4 v1 = base[(size_t)32 * stride];
    float4 v2 = base[(size_t)64 * stride];
    float4 v3 = base[(size_t)96 * stride];
    float4 v4 = make_float4(0.f, 0.f, 0.f, 0.f);
    if (gp < GRID1 - 128)
        v4 = base[(size_t)128 * stride];

    float4 acc;
    acc.x = (v0.x + v1.x) + (v2.x + v3.x) + v4.x;
    acc.y = (v0.y + v1.y) + (v2.y + v3.y) + v4.y;
    acc.z = (v0.z + v1.z) + (v2.z + v3.z) + v4.z;
    acc.w = (v0.w + v1.w) + (v2.w + v3.w) + v4.w;
    red[gp * 16 + a4] = acc;
    __syncthreads();

    #pragma unroll
    for (int s = 16; s > 0; s >>= 1) {
        if (gp < s) {
            float4 a = red[gp * 16 + a4];
            float4 b = red[(gp + s) * 16 + a4];
            a.x += b.x; a.y += b.y; a.z += b.z; a.w += b.w;
            red[gp * 16 + a4] = a;
        }
        __syncthreads();
    }

    if (t < 16) {
        float cnt = 0.f;
        #pragma unroll
        for (int w = 0; w < 16; w++) cnt += wcnt[w];
        const float inv = 1.f / ((cnt == 0.f) ? 1.f : cnt);
        float4 sum = red[a4];
        float4 mean = make_float4(sum.x * inv, sum.y * inv, sum.z * inv, sum.w * inv);

        float4* out4 = reinterpret_cast<float4*>(out);
        const int oidx = c * A4 + agrp * 16 + a4;
        out4[oidx] = mean;                                         // mean (C, A)
        out4[NUM_C * A4 + oidx] = make_float4(cnt, cnt, cnt, cnt); // sum_weight
        if (t == 0 && agrp == 0)
            out[2 * NUM_C * NUM_A + c] = cnt;                      // class_dist (C,)
    }

    // ---- counter self-reset so graph replays start from zero ----
    if (t == 0) {
        const int v = atomicAdd(&g_fin, 1);
        if (v == NFIN - 1) {               // all finalize blocks passed the gate
            g_fin  = 0;
            g_done = 0;
            __threadfence();
        }
    }
}

__global__ void __launch_bounds__(TPB1, 1) bars_fused_kernel(
    const float4* __restrict__ feat,
    const int*    __restrict__ labels,
    const int*    __restrict__ ignore_ptr,
    int N, float* __restrict__ out)
{
    extern __shared__ float4 smem4[];
    if (blockIdx.x < GRID1)
        accum_part(feat, labels, ignore_ptr, N, smem4);
    else
        finalize_part(out, smem4);
}

extern "C" void kernel_launch(void* const* d_in, const int* in_sizes, int n_in,
                              void* d_out, int out_size)
{
    const float4* feat   = (const float4*)d_in[0];
    const int*    labels = (const int*)d_in[1];
    const int*    ign    = (const int*)d_in[2];
    float*        out    = (float*)d_out;

    const int N = in_sizes[0] / NUM_A;

    cudaFuncSetAttribute(bars_fused_kernel,
                         cudaFuncAttributeMaxDynamicSharedMemorySize, SMEM_BYTES);

    bars_fused_kernel<<<GRID1 + NFIN, TPB1, SMEM_BYTES>>>(feat, labels, ign, N, out);
}

// round 16
// speedup vs baseline: 1.0386x; 1.0025x over previous
#include <cuda_runtime.h>

#define NUM_C 19
#define NUM_A 512            // feature channels
#define A4 (NUM_A / 4)       // float4 per row = 128
#define GRID1 148            // 1 block per SM, single wave (all co-resident)
#define NUNITS (NUM_C * 8)   // 152 finalize units
#define TPB1 512             // 4 warpgroups of 128 threads
#define CPAD 20              // padded class stride for count buckets

// Per-warpgroup replica layout inside dynamic smem:
//   float4 ssum[4][NUM_C * A4]   (155648 B)
//   float  scnt[16][CPAD]        (1280 B)
#define SMEM_SSUM_F4 (4 * NUM_C * A4)
#define SMEM_BYTES   (SMEM_SSUM_F4 * 16 + 16 * CPAD * 4)

// Deterministic partial-sum scratch (no device-side allocation allowed).
__device__ float g_psums[(size_t)GRID1 * NUM_C * NUM_A]; // [g][c][a]  ~5.8 MB
__device__ float g_pcnts[GRID1 * NUM_C];                 // [g][c]
__device__ int   g_done;                                 // accum blocks finished
__device__ int   g_fin;                                  // blocks finished all work

// ---- 8-row batch helpers (software pipeline) ----
#define LOAD_BATCH(RR, LAB, F)                                              \
    do {                                                                    \
        const int4 L0 = __ldg((const int4*)&labels[(RR)]);                  \
        const int4 L1 = __ldg((const int4*)&labels[(RR) + 4]);              \
        LAB[0] = L0.x; LAB[1] = L0.y; LAB[2] = L0.z; LAB[3] = L0.w;         \
        LAB[4] = L1.x; LAB[5] = L1.y; LAB[6] = L1.z; LAB[7] = L1.w;         \
        _Pragma("unroll")                                                   \
        for (int j = 0; j < 8; j++)                                         \
            if (LAB[j] != ign)                                              \
                F[j] = __ldcs(&feat[(size_t)((RR) + j) * A4 + tt]);         \
    } while (0)

#define RMW_BATCH(LAB, F)                                                   \
    do {                                                                    \
        _Pragma("unroll")                                                   \
        for (int j = 0; j < 8; j++) {                                       \
            if (LAB[j] != ign) {                                            \
                const int idx = LAB[j] * A4 + tt;                           \
                float4 s = ssum[idx];                                       \
                s.x += F[j].x; s.y += F[j].y; s.z += F[j].z; s.w += F[j].w; \
                ssum[idx] = s;                                              \
            }                                                               \
        }                                                                   \
        if (lane == 0) {                                                    \
            _Pragma("unroll")                                               \
            for (int j = 0; j < 2; j++) {                                   \
                const int jj = wgw * 2 + j;                                 \
                if (LAB[jj] != ign) scnt[warp * CPAD + LAB[jj]] += 1.f;     \
            }                                                               \
        }                                                                   \
    } while (0)

__global__ void __launch_bounds__(TPB1, 1) bars_fused_kernel(
    const float4* __restrict__ feat,
    const int*    __restrict__ labels,
    const int*    __restrict__ ignore_ptr,
    int N, float* __restrict__ out)
{
    extern __shared__ float4 smem4[];
    const int t    = threadIdx.x;
    const int wg   = t >> 7;        // warpgroup 0..3
    const int tt   = t & 127;       // float4 channel within warpgroup
    const int warp = t >> 5;        // 0..15
    const int wgw  = warp & 3;      // warp within warpgroup
    const int lane = t & 31;

    float4* ssum = smem4 + (size_t)wg * (NUM_C * A4);     // this wg's replica
    float*  scnt = (float*)(smem4 + SMEM_SSUM_F4);        // [16][CPAD]

    #pragma unroll
    for (int i = t; i < SMEM_SSUM_F4; i += TPB1)
        smem4[i] = make_float4(0.f, 0.f, 0.f, 0.f);
    if (t < 16 * CPAD) scnt[t] = 0.f;
    __syncthreads();

    const int ign   = *ignore_ptr;
    // rows per block rounded to 32 so warpgroup chunks stay 8-aligned
    const int rowsb = (((N + GRID1 - 1) / GRID1) + 31) & ~31;
    const int r0b   = blockIdx.x * rowsb;
    const int r1b   = min(r0b + rowsb, N);

    const int nb    = max(r1b - r0b, 0);
    int chunk = (nb + 3) >> 2;
    chunk = (chunk + 7) & ~7;                             // 8-aligned
    const int r0    = min(r0b + wg * chunk, r1b);
    const int r1    = min(r0 + chunk, r1b);

    const int nfull = (r1 - r0) >> 3;       // full 8-row batches

    {
        int    labA[8], labB[8];
        float4 fA[8],   fB[8];

        if (nfull > 0) LOAD_BATCH(r0, labA, fA);

        int b = 0;
        // Pipelined main loop: prefetch batch b+1 before consuming batch b.
        for (; b + 2 < nfull; b += 2) {
            LOAD_BATCH(r0 + (b + 1) * 8, labB, fB);
            RMW_BATCH(labA, fA);
            LOAD_BATCH(r0 + (b + 2) * 8, labA, fA);
            RMW_BATCH(labB, fB);
        }
        if (nfull > 0) {
            if (b + 1 < nfull) {
                LOAD_BATCH(r0 + (b + 1) * 8, labB, fB);
                RMW_BATCH(labA, fA);
                RMW_BATCH(labB, fB);
            } else {
                RMW_BATCH(labA, fA);
            }
        }
        // scalar tail
        for (int r = r0 + nfull * 8; r < r1; r++) {
            const int lab = __ldg(&labels[r]);
            if (lab != ign) {
                float4 f = __ldcs(&feat[(size_t)r * A4 + tt]);
                const int idx = lab * A4 + tt;
                float4 s = ssum[idx];
                s.x += f.x; s.y += f.y; s.z += f.z; s.w += f.w;
                ssum[idx] = s;
                if (tt == 0) scnt[(wg * 4) * CPAD + lab] += 1.f;
            }
        }
    }
    __syncthreads();

    // Reduce the 4 warpgroup replicas and store one slab per block.
    float4* pout = reinterpret_cast<float4*>(g_psums) + (size_t)blockIdx.x * NUM_C * A4;
    #pragma unroll
    for (int i = t; i < NUM_C * A4; i += TPB1) {
        float4 a  = smem4[i];
        float4 bb = smem4[i + NUM_C * A4];
        float4 c4 = smem4[i + 2 * NUM_C * A4];
        float4 d  = smem4[i + 3 * NUM_C * A4];
        a.x = (a.x + bb.x) + (c4.x + d.x);
        a.y = (a.y + bb.y) + (c4.y + d.y);
        a.z = (a.z + bb.z) + (c4.z + d.z);
        a.w = (a.w + bb.w) + (c4.w + d.w);
        pout[i] = a;
    }
    if (t < NUM_C) {
        float cl = 0.f;
        #pragma unroll
        for (int w = 0; w < 16; w++) cl += scnt[w * CPAD + t];
        g_pcnts[blockIdx.x * NUM_C + t] = cl;
    }
    __syncthreads();
    __threadfence();                       // release psums/pcnts
    if (t == 0) atomicAdd(&g_done, 1);

    // ---- gate: all 148 blocks co-resident (one wave) -> spin is safe ----
    if (t == 0) {
        while (atomicAdd(&g_done, 0) < GRID1)
            __nanosleep(128);
    }
    __syncthreads();
    __threadfence();                       // acquire psums/pcnts

    // ============ in-place finalize, dual units processed in PARALLEL ======
    // unit u: class c = u >> 3, channel group agrp = u & 7 (16 float4 each).
    // Block b does unit b; blocks 0..3 also do unit 148+b concurrently
    // (all loads issued before any fold -> no serial round-trip).
    {
        const int a4   = t & 15;    // 0..15
        const int gp   = t >> 4;    // 0..31

        const int  u1   = blockIdx.x;
        const bool dual = (blockIdx.x < NUNITS - GRID1);   // blocks 0..3
        const int  u2   = GRID1 + blockIdx.x;

        const int c1 = u1 >> 3, ag1 = u1 & 7;
        const int c2 = u2 >> 3, ag2 = u2 & 7;

        float4* red1 = smem4;          // [32][16]
        float4* red2 = smem4 + 512;    // [32][16]
        __shared__ float wcnt1[16], wcnt2[16];

        const float4* ps = reinterpret_cast<const float4*>(g_psums);
        const size_t stride = (size_t)NUM_C * A4;

        // per-class counts for both units (independent loads, overlap)
        {
            float cl1 = (t < GRID1) ? g_pcnts[t * NUM_C + c1] : 0.f;
            float cl2 = 0.f;
            if (dual && t < GRID1) cl2 = g_pcnts[t * NUM_C + c2];
            #pragma unroll
            for (int o = 16; o > 0; o >>= 1) {
                cl1 += __shfl_down_sync(0xFFFFFFFFu, cl1, o);
                cl2 += __shfl_down_sync(0xFFFFFFFFu, cl2, o);
            }
            if (lane == 0) { wcnt1[warp] = cl1; wcnt2[warp] = cl2; }
        }

        // unit 1 loads: g = gp + 32*k, k = 0..3, + pred g = 128+gp
        const float4* b1 = ps + (size_t)c1 * A4 + ag1 * 16 + a4 + (size_t)gp * stride;
        float4 x0 = b1[0];
        float4 x1 = b1[(size_t)32 * stride];
        float4 x2 = b1[(size_t)64 * stride];
        float4 x3 = b1[(size_t)96 * stride];
        float4 x4 = make_float4(0.f, 0.f, 0.f, 0.f);
        if (gp < GRID1 - 128) x4 = b1[(size_t)128 * stride];

        // unit 2 loads (only blocks 0..3) — issued before any fold
        float4 y0, y1, y2, y3, y4;
        if (dual) {
            const float4* b2 = ps + (size_t)c2 * A4 + ag2 * 16 + a4 + (size_t)gp * stride;
            y0 = b2[0];
            y1 = b2[(size_t)32 * stride];
            y2 = b2[(size_t)64 * stride];
            y3 = b2[(size_t)96 * stride];
            y4 = make_float4(0.f, 0.f, 0.f, 0.f);
            if (gp < GRID1 - 128) y4 = b2[(size_t)128 * stride];
        }

        float4 acc;
        acc.x = (x0.x + x1.x) + (x2.x + x3.x) + x4.x;
        acc.y = (x0.y + x1.y) + (x2.y + x3.y) + x4.y;
        acc.z = (x0.z + x1.z) + (x2.z + x3.z) + x4.z;
        acc.w = (x0.w + x1.w) + (x2.w + x3.w) + x4.w;
        red1[gp * 16 + a4] = acc;
        if (dual) {
            acc.x = (y0.x + y1.x) + (y2.x + y3.x) + y4.x;
            acc.y = (y0.y + y1.y) + (y2.y + y3.y) + y4.y;
            acc.z = (y0.z + y1.z) + (y2.z + y3.z) + y4.z;
            acc.w = (y0.w + y1.w) + (y2.w + y3.w) + y4.w;
            red2[gp * 16 + a4] = acc;
        }
        __syncthreads();

        // Fold 32 g-partitions -> 1, both red arrays in the same sweep.
        #pragma unroll
        for (int s = 16; s > 0; s >>= 1) {
            if (gp < s) {
                float4 a = red1[gp * 16 + a4];
                float4 b = red1[(gp + s) * 16 + a4];
                a.x += b.x; a.y += b.y; a.z += b.z; a.w += b.w;
                red1[gp * 16 + a4] = a;
                if (dual) {
                    float4 a2 = red2[gp * 16 + a4];
                    float4 b2v = red2[(gp + s) * 16 + a4];
                    a2.x += b2v.x; a2.y += b2v.y; a2.z += b2v.z; a2.w += b2v.w;
                    red2[gp * 16 + a4] = a2;
                }
            }
            __syncthreads();
        }

        if (t < 16) {
            float4* out4 = reinterpret_cast<float4*>(out);

            float cnt1 = 0.f;
            #pragma unroll
            for (int w = 0; w < 16; w++) cnt1 += wcnt1[w];
            const float inv1 = 1.f / ((cnt1 == 0.f) ? 1.f : cnt1);
            float4 s1 = red1[a4];
            const int o1 = c1 * A4 + ag1 * 16 + a4;
            out4[o1] = make_float4(s1.x * inv1, s1.y * inv1, s1.z * inv1, s1.w * inv1);
            out4[NUM_C * A4 + o1] = make_float4(cnt1, cnt1, cnt1, cnt1);
            if (t == 0 && ag1 == 0)
                out[2 * NUM_C * NUM_A + c1] = cnt1;

            if (dual) {
                float cnt2 = 0.f;
                #pragma unroll
                for (int w = 0; w < 16; w++) cnt2 += wcnt2[w];
                const float inv2 = 1.f / ((cnt2 == 0.f) ? 1.f : cnt2);
                float4 s2 = red2[a4];
                const int o2 = c2 * A4 + ag2 * 16 + a4;
                out4[o2] = make_float4(s2.x * inv2, s2.y * inv2, s2.z * inv2, s2.w * inv2);
                out4[NUM_C * A4 + o2] = make_float4(cnt2, cnt2, cnt2, cnt2);
                if (t == 0 && ag2 == 0)
                    out[2 * NUM_C * NUM_A + c2] = cnt2;
            }
        }
    }

    // ---- counter self-reset so graph replays start from zero ----
    if (t == 0) {
        const int v = atomicAdd(&g_fin, 1);
        if (v == GRID1 - 1) {              // last block out resets both
            g_fin  = 0;
            g_done = 0;
            __threadfence();
        }
    }
}

extern "C" void kernel_launch(void* const* d_in, const int* in_sizes, int n_in,
                              void* d_out, int out_size)
{
    const float4* feat   = (const float4*)d_in[0];
    const int*    labels = (const int*)d_in[1];
    const int*    ign    = (const int*)d_in[2];
    float*        out    = (float*)d_out;

    const int N = in_sizes[0] / NUM_A;

    cudaFuncSetAttribute(bars_fused_kernel,
                         cudaFuncAttributeMaxDynamicSharedMemorySize, SMEM_BYTES);

    bars_fused_kernel<<<GRID1, TPB1, SMEM_BYTES>>>(feat, labels, ign, N, out);
}